// round 2
// baseline (speedup 1.0000x reference)
#include <cuda_runtime.h>

#define D 128
#define MAXN 50048
#define MAXE 700000

// ---------------- scratch (no allocations allowed) ----------------
__device__ float g_h[(size_t)MAXN * D];    // GEMM output (both layers)
__device__ float g_agg[(size_t)MAXN * D];  // layer-1 aggregation / activation
__device__ float g_deg[MAXN];
__device__ float g_dinv[MAXN];
__device__ int   g_src[MAXE];
__device__ int   g_dst[MAXE];
__device__ int   g_is32;                   // 1 if edge_index buffer is int32

// ---------------- zero scratch: g_deg + g_agg + g_is32 ----------------
__global__ void zero_scratch_kernel(int N) {
    long idx = (long)blockIdx.x * blockDim.x + threadIdx.x;
    long tot4 = (long)N * (D / 4);
    if (idx < tot4) reinterpret_cast<float4*>(g_agg)[idx] = make_float4(0.f, 0.f, 0.f, 0.f);
    if (idx < N) g_deg[idx] = 0.f;
    if (idx == 0) g_is32 = 0;
}

__global__ void zero_out_kernel(float4* __restrict__ out, long n4) {
    long idx = (long)blockIdx.x * blockDim.x + threadIdx.x;
    if (idx < n4) out[idx] = make_float4(0.f, 0.f, 0.f, 0.f);
}

// ---------------- edge dtype detection + decode ----------------
// If the buffer truly holds int64 node ids, every 8-byte value is < N.
// If it holds int32 ids, an 8-byte read combines two ids; the high word is a
// node id that is nonzero for almost every edge -> value >= 2^32 >> N.
__global__ void detect_kernel(const unsigned long long* __restrict__ ei,
                              int E, unsigned long long limit) {
    int e = blockIdx.x * blockDim.x + threadIdx.x;
    if (e < 2 * E) {
        if (ei[e] >= limit) atomicOr(&g_is32, 1);
    }
}

__global__ void decode_kernel(const void* __restrict__ ei, int E) {
    int e = blockIdx.x * blockDim.x + threadIdx.x;
    if (e >= E) return;
    if (g_is32) {
        const int* p = (const int*)ei;
        g_src[e] = p[e];
        g_dst[e] = p[E + e];
    } else {
        const long long* p = (const long long*)ei;
        g_src[e] = (int)p[e];
        g_dst[e] = (int)p[E + e];
    }
}

// ---------------- degree + symmetric norm ----------------
__global__ void deg_kernel(int E) {
    int e = blockIdx.x * blockDim.x + threadIdx.x;
    if (e < E) atomicAdd(&g_deg[g_dst[e]], 1.0f);
}

__global__ void dinv_kernel(int N) {
    int i = blockIdx.x * blockDim.x + threadIdx.x;
    if (i < N) g_dinv[i] = rsqrtf(g_deg[i] + 1.0f);  // +1 for the self-loop
}

// ---------------- GEMM: g_h[N,128] = X[N,128] @ W[128,128] ----------------
// 128 threads/CTA (one per output column), 32 rows per CTA in smem.
__global__ __launch_bounds__(128) void gemm128_kernel(
    const float* __restrict__ Xin, int use_agg,
    const float* __restrict__ W, int N)
{
    __shared__ float xs[32][D];
    const float* X = use_agg ? g_agg : Xin;
    const int t  = threadIdx.x;            // output column
    const int r0 = blockIdx.x * 32;
    const int rows = min(32, N - r0);

    {
        const float4* Xv = reinterpret_cast<const float4*>(X + (size_t)r0 * D);
        float4* xsv = reinterpret_cast<float4*>(&xs[0][0]);
        int tot = rows * (D / 4);
        for (int idx = t; idx < tot; idx += 128) xsv[idx] = Xv[idx];
    }
    __syncthreads();

    float acc[32];
#pragma unroll
    for (int r = 0; r < 32; r++) acc[r] = 0.f;

#pragma unroll 4
    for (int kc = 0; kc < D; kc += 8) {
        float w[8];
#pragma unroll
        for (int i = 0; i < 8; i++) w[i] = W[(kc + i) * D + t];
#pragma unroll
        for (int r = 0; r < 32; r++) {
            float4 a = *reinterpret_cast<const float4*>(&xs[r][kc]);
            float4 b = *reinterpret_cast<const float4*>(&xs[r][kc + 4]);
            acc[r] += a.x * w[0] + a.y * w[1] + a.z * w[2] + a.w * w[3]
                    + b.x * w[4] + b.y * w[5] + b.z * w[6] + b.w * w[7];
        }
    }

    for (int r = 0; r < rows; r++)
        g_h[(size_t)(r0 + r) * D + t] = acc[r];
}

// ---------------- edge scatter: AGG[dst] += g_h[src] * dinv[src]*dinv[dst] ---
// One warp per edge; lane handles 4 contiguous columns.
__global__ __launch_bounds__(256) void scatter_kernel(
    float* __restrict__ out_ptr, int use_out, int E)
{
    int warp = (blockIdx.x * blockDim.x + threadIdx.x) >> 5;
    int lane = threadIdx.x & 31;
    if (warp >= E) return;

    int s = g_src[warp];
    int d = g_dst[warp];
    float norm = g_dinv[s] * g_dinv[d];

    float4 v = *reinterpret_cast<const float4*>(&g_h[(size_t)s * D + lane * 4]);
    float* agg = (use_out ? out_ptr : g_agg) + (size_t)d * D + lane * 4;
    atomicAdd(agg + 0, v.x * norm);
    atomicAdd(agg + 1, v.y * norm);
    atomicAdd(agg + 2, v.z * norm);
    atomicAdd(agg + 3, v.w * norm);
}

// ---------------- epilogue: AGG += g_h * dinv^2 (self loop) + bias; opt ReLU -
__global__ __launch_bounds__(256) void epi_kernel(
    float* __restrict__ out_ptr, int use_out,
    const float* __restrict__ bias, int N, int do_relu)
{
    long idx = (long)blockIdx.x * blockDim.x + threadIdx.x;  // float4 index
    long tot4 = (long)N * (D / 4);
    if (idx >= tot4) return;

    int i  = (int)(idx >> 5);        // row (32 float4 per row)
    int j4 = ((int)idx & 31) * 4;    // column base

    float di = g_dinv[i];
    float sl = di * di;

    float4* aggp = (use_out ? reinterpret_cast<float4*>(out_ptr)
                            : reinterpret_cast<float4*>(g_agg)) + idx;
    float4 a = *aggp;
    float4 h = reinterpret_cast<const float4*>(g_h)[idx];
    float4 b = *reinterpret_cast<const float4*>(&bias[j4]);

    a.x += h.x * sl + b.x;
    a.y += h.y * sl + b.y;
    a.z += h.z * sl + b.z;
    a.w += h.w * sl + b.w;
    if (do_relu) {
        a.x = fmaxf(a.x, 0.f); a.y = fmaxf(a.y, 0.f);
        a.z = fmaxf(a.z, 0.f); a.w = fmaxf(a.w, 0.f);
    }
    *aggp = a;
}

// ---------------- launch ----------------
extern "C" void kernel_launch(void* const* d_in, const int* in_sizes, int n_in,
                              void* d_out, int out_size) {
    const float* x   = (const float*)d_in[0];
    const void*  ei  = d_in[1];
    const float* W1  = (const float*)d_in[2];
    const float* b1  = (const float*)d_in[3];
    const float* W2  = (const float*)d_in[4];
    const float* b2  = (const float*)d_in[5];
    float*       out = (float*)d_out;

    const int N = in_sizes[0] / D;
    const int E = in_sizes[1] / 2;

    const long n4 = (long)N * (D / 4);
    const int TB = 256;
    const int zs_blocks   = (int)((n4 + TB - 1) / TB);
    const int e_blocks    = (E + TB - 1) / TB;
    const int e2_blocks   = (2 * E + TB - 1) / TB;
    const int n_blocks    = (N + TB - 1) / TB;
    const int gemm_blocks = (N + 31) / 32;
    const int sc_blocks   = (int)(((long)E * 32 + TB - 1) / TB);
    const int epi_blocks  = (int)((n4 + TB - 1) / TB);

    // setup: zero scratch + out, decode edges (dtype-robust), degree + norm
    zero_scratch_kernel<<<zs_blocks, TB>>>(N);              // g_agg=0, g_deg=0, g_is32=0
    zero_out_kernel<<<zs_blocks, TB>>>((float4*)out, n4);   // d_out is poisoned
    // When the buffer is int32, it holds 2E int32 = E "int64" slots; when
    // int64 it holds 2E slots. Scan E slots: enough to hit a high word.
    detect_kernel<<<e_blocks, TB>>>((const unsigned long long*)ei, E / 2,
                                    (unsigned long long)N);
    decode_kernel<<<e_blocks, TB>>>(ei, E);
    deg_kernel<<<e_blocks, TB>>>(E);
    dinv_kernel<<<n_blocks, TB>>>(N);

    // layer 1: h = x@W1 ; agg = scatter(h) ; agg = relu(agg + h*dinv^2 + b1)
    gemm128_kernel<<<gemm_blocks, 128>>>(x, 0, W1, N);
    scatter_kernel<<<sc_blocks, TB>>>(out, 0, E);
    epi_kernel<<<epi_blocks, TB>>>(out, 0, b1, N, 1);

    // layer 2: h = agg@W2 ; out = scatter(h) ; out += h*dinv^2 + b2
    gemm128_kernel<<<gemm_blocks, 128>>>(x, 1, W2, N);
    scatter_kernel<<<sc_blocks, TB>>>(out, 1, E);
    epi_kernel<<<epi_blocks, TB>>>(out, 1, b2, N, 0);
}

// round 3
// speedup vs baseline: 1.6993x; 1.6993x over previous
#include <cuda_runtime.h>

#define D 128
#define MAXN 50051
#define MAXE 700000

// ---------------- scratch (no allocations allowed) ----------------
__device__ float g_h[(size_t)MAXN * D];    // GEMM output, pre-scaled by dinv[src]
__device__ float g_agg[(size_t)MAXN * D];  // layer-1 activation
__device__ float g_dinv[MAXN];
__device__ int   g_degi[MAXN];             // int in-degree histogram
__device__ int   g_cnt[MAXN];              // CSR fill cursors
__device__ int   g_rowptr[MAXN + 1];
__device__ int   g_src[MAXE];
__device__ int   g_dst[MAXE];
__device__ int   g_csr[MAXE];              // src indices grouped by dst
__device__ int   g_is32;

// ---------------- init: zero histograms + flag ----------------
__global__ void init_kernel(int N) {
    int i = blockIdx.x * blockDim.x + threadIdx.x;
    if (i < N) { g_degi[i] = 0; g_cnt[i] = 0; }
    if (i == 0) g_is32 = 0;
}

// ---------------- edge dtype detection ----------------
// int64 node ids are < N; int32 pairs read as uint64 are >= 2^32 whenever the
// high word (a node id) is nonzero — true for almost every edge.
__global__ void detect_kernel(const unsigned long long* __restrict__ ei,
                              int n, unsigned long long limit) {
    int e = blockIdx.x * blockDim.x + threadIdx.x;
    if (e < n && ei[e] >= limit) atomicOr(&g_is32, 1);
}

// ---------------- decode edges + in-degree histogram ----------------
__global__ void decode_kernel(const void* __restrict__ ei, int E) {
    int e = blockIdx.x * blockDim.x + threadIdx.x;
    if (e >= E) return;
    int s, d;
    if (g_is32) {
        const int* p = (const int*)ei;
        s = p[e]; d = p[E + e];
    } else {
        const long long* p = (const long long*)ei;
        s = (int)p[e]; d = (int)p[E + e];
    }
    g_src[e] = s;
    g_dst[e] = d;
    atomicAdd(&g_degi[d], 1);
}

// ---------------- single-block scan: rowptr (exclusive) + dinv ----------------
__global__ __launch_bounds__(1024) void scan_kernel(int N) {
    __shared__ int sh[1024];
    __shared__ int s_off;
    int tid = threadIdx.x;
    if (tid == 0) { s_off = 0; g_rowptr[0] = 0; }
    __syncthreads();
    for (int base = 0; base < N; base += 1024) {
        int i = base + tid;
        int v = (i < N) ? g_degi[i] : 0;
        sh[tid] = v;
        __syncthreads();
        for (int dstep = 1; dstep < 1024; dstep <<= 1) {
            int t = (tid >= dstep) ? sh[tid - dstep] : 0;
            __syncthreads();
            sh[tid] += t;
            __syncthreads();
        }
        if (i < N) {
            g_rowptr[i + 1] = s_off + sh[tid];          // inclusive + offset
            g_dinv[i] = rsqrtf((float)v + 1.0f);        // +1 self-loop
        }
        __syncthreads();
        if (tid == 0) s_off += sh[1023];
        __syncthreads();
    }
}

// ---------------- counting-sort edges into CSR (grouped by dst) -------------
__global__ void csr_fill_kernel(int E) {
    int e = blockIdx.x * blockDim.x + threadIdx.x;
    if (e >= E) return;
    int d = g_dst[e];
    int pos = g_rowptr[d] + atomicAdd(&g_cnt[d], 1);
    g_csr[pos] = g_src[e];
}

// ---------------- GEMM: g_h[N,128] = (X[N,128] @ W[128,128]) * dinv[row] ----
// 128 threads/CTA (one per output column), 32 rows per CTA in smem.
__global__ __launch_bounds__(128) void gemm128_kernel(
    const float* __restrict__ Xin, int use_agg,
    const float* __restrict__ W, int N)
{
    __shared__ float xs[32][D];
    const float* X = use_agg ? g_agg : Xin;
    const int t  = threadIdx.x;            // output column
    const int r0 = blockIdx.x * 32;
    const int rows = min(32, N - r0);

    {
        const float4* Xv = reinterpret_cast<const float4*>(X + (size_t)r0 * D);
        float4* xsv = reinterpret_cast<float4*>(&xs[0][0]);
        int tot = rows * (D / 4);
        for (int idx = t; idx < tot; idx += 128) xsv[idx] = Xv[idx];
    }
    __syncthreads();

    float acc[32];
#pragma unroll
    for (int r = 0; r < 32; r++) acc[r] = 0.f;

#pragma unroll 4
    for (int kc = 0; kc < D; kc += 8) {
        float w[8];
#pragma unroll
        for (int i = 0; i < 8; i++) w[i] = W[(kc + i) * D + t];
#pragma unroll
        for (int r = 0; r < 32; r++) {
            float4 a = *reinterpret_cast<const float4*>(&xs[r][kc]);
            float4 b = *reinterpret_cast<const float4*>(&xs[r][kc + 4]);
            acc[r] += a.x * w[0] + a.y * w[1] + a.z * w[2] + a.w * w[3]
                    + b.x * w[4] + b.y * w[5] + b.z * w[6] + b.w * w[7];
        }
    }

    for (int r = 0; r < rows; r++)
        g_h[(size_t)(r0 + r) * D + t] = acc[r] * g_dinv[r0 + r];
}

// ---------------- gather aggregation (no atomics) ----------------------------
// out[d] = dinv[d] * (h_scaled[d] + sum_{s in nbr(d)} h_scaled[s]) + bias
// One warp per dst node; lane handles 4 contiguous columns.
__global__ __launch_bounds__(256) void agg_kernel(
    float* __restrict__ out_base, int use_out,
    const float* __restrict__ bias, int N, int do_relu)
{
    int node = (blockIdx.x * blockDim.x + threadIdx.x) >> 5;
    int lane = threadIdx.x & 31;
    if (node >= N) return;

    int beg = g_rowptr[node];
    int end = g_rowptr[node + 1];

    // self-loop term: this row's own pre-scaled value
    float4 acc = *reinterpret_cast<const float4*>(&g_h[(size_t)node * D + lane * 4]);

    for (int j0 = beg; j0 < end; j0 += 32) {
        int jj = j0 + lane;
        int sj = (jj < end) ? g_csr[jj] : 0;
        int cnt = min(32, end - j0);
        for (int k = 0; k < cnt; k++) {
            int s = __shfl_sync(0xffffffffu, sj, k);
            float4 v = *reinterpret_cast<const float4*>(&g_h[(size_t)s * D + lane * 4]);
            acc.x += v.x; acc.y += v.y; acc.z += v.z; acc.w += v.w;
        }
    }

    float dn = g_dinv[node];
    float4 b = *reinterpret_cast<const float4*>(&bias[lane * 4]);
    float4 o;
    o.x = acc.x * dn + b.x;
    o.y = acc.y * dn + b.y;
    o.z = acc.z * dn + b.z;
    o.w = acc.w * dn + b.w;
    if (do_relu) {
        o.x = fmaxf(o.x, 0.f); o.y = fmaxf(o.y, 0.f);
        o.z = fmaxf(o.z, 0.f); o.w = fmaxf(o.w, 0.f);
    }
    float* outp = use_out ? out_base : g_agg;
    *reinterpret_cast<float4*>(&outp[(size_t)node * D + lane * 4]) = o;
}

// ---------------- launch ----------------
extern "C" void kernel_launch(void* const* d_in, const int* in_sizes, int n_in,
                              void* d_out, int out_size) {
    const float* x   = (const float*)d_in[0];
    const void*  ei  = d_in[1];
    const float* W1  = (const float*)d_in[2];
    const float* b1  = (const float*)d_in[3];
    const float* W2  = (const float*)d_in[4];
    const float* b2  = (const float*)d_in[5];
    float*       out = (float*)d_out;

    const int N = in_sizes[0] / D;
    const int E = in_sizes[1] / 2;

    const int TB = 256;
    const int n_blocks    = (N + TB - 1) / TB;
    const int e_blocks    = (E + TB - 1) / TB;
    const int gemm_blocks = (N + 31) / 32;
    const int agg_blocks  = (int)(((long)N * 32 + TB - 1) / TB);

    // ---- graph preprocessing (shared by both layers) ----
    init_kernel<<<n_blocks, TB>>>(N);
    detect_kernel<<<e_blocks, TB>>>((const unsigned long long*)ei, E / 2,
                                    (unsigned long long)N);
    decode_kernel<<<e_blocks, TB>>>(ei, E);
    scan_kernel<<<1, 1024>>>(N);
    csr_fill_kernel<<<e_blocks, TB>>>(E);

    // ---- layer 1: h = (x@W1)*dinv ; agg = relu(dinv*(self+nbrs) + b1) ----
    gemm128_kernel<<<gemm_blocks, 128>>>(x, 0, W1, N);
    agg_kernel<<<agg_blocks, TB>>>(out, 0, b1, N, 1);

    // ---- layer 2: h = (agg@W2)*dinv ; out = dinv*(self+nbrs) + b2 ----
    gemm128_kernel<<<gemm_blocks, 128>>>(x, 1, W2, N);
    agg_kernel<<<agg_blocks, TB>>>(out, 1, b2, N, 0);
}

// round 4
// speedup vs baseline: 2.1301x; 1.2535x over previous
#include <cuda_runtime.h>

#define D 128
#define MAXN 50051
#define MAXE 700000
#define SCAN_B 1024

// ---------------- scratch (no allocations allowed) ----------------
__device__ float g_h[(size_t)MAXN * D];    // GEMM output, pre-scaled by dinv[src]
__device__ float g_agg[(size_t)MAXN * D];  // layer-1 activation
__device__ float g_dinv[MAXN];
__device__ int   g_degi[MAXN];             // int in-degree histogram
__device__ int   g_cnt[MAXN];              // CSR fill cursors
__device__ int   g_rowptr[MAXN + 1];
__device__ int   g_src[MAXE];
__device__ int   g_dst[MAXE];
__device__ int   g_csr[MAXE];              // src indices grouped by dst
__device__ int   g_bsum[128];              // per-block scan totals
__device__ int   g_boff[128];              // exclusive-scanned block offsets
__device__ int   g_is32;

// ---------------- init: zero histograms + flag ----------------
__global__ void init_kernel(int N) {
    int i = blockIdx.x * blockDim.x + threadIdx.x;
    if (i < N) { g_degi[i] = 0; g_cnt[i] = 0; }
    if (i == 0) g_is32 = 0;
}

// ---------------- edge dtype detection ----------------
// int64 node ids are < N; int32 pairs read as uint64 are >= 2^32 whenever the
// high word (a node id) is nonzero — true for almost every edge.
__global__ void detect_kernel(const unsigned long long* __restrict__ ei,
                              int n, unsigned long long limit) {
    int e = blockIdx.x * blockDim.x + threadIdx.x;
    if (e < n && ei[e] >= limit) atomicOr(&g_is32, 1);
}

// ---------------- decode edges + in-degree histogram ----------------
__global__ void decode_kernel(const void* __restrict__ ei, int E) {
    int e = blockIdx.x * blockDim.x + threadIdx.x;
    if (e >= E) return;
    int s, d;
    if (g_is32) {
        const int* p = (const int*)ei;
        s = p[e]; d = p[E + e];
    } else {
        const long long* p = (const long long*)ei;
        s = (int)p[e]; d = (int)p[E + e];
    }
    g_src[e] = s;
    g_dst[e] = d;
    atomicAdd(&g_degi[d], 1);
}

// ---------------- phase 1: per-block inclusive scan (+ dinv) ----------------
__global__ __launch_bounds__(SCAN_B) void block_scan_kernel(int N) {
    __shared__ int wsum[SCAN_B / 32];
    int tid  = threadIdx.x;
    int lane = tid & 31;
    int wid  = tid >> 5;
    int i = blockIdx.x * SCAN_B + tid;

    int v = (i < N) ? g_degi[i] : 0;

    // warp inclusive scan
    int s = v;
#pragma unroll
    for (int o = 1; o < 32; o <<= 1) {
        int t = __shfl_up_sync(0xffffffffu, s, o);
        if (lane >= o) s += t;
    }
    if (lane == 31) wsum[wid] = s;
    __syncthreads();

    // scan the 32 warp sums with warp 0
    if (wid == 0) {
        int ws = wsum[lane];
#pragma unroll
        for (int o = 1; o < 32; o <<= 1) {
            int t = __shfl_up_sync(0xffffffffu, ws, o);
            if (lane >= o) ws += t;
        }
        wsum[lane] = ws;
    }
    __syncthreads();

    int incl = s + (wid > 0 ? wsum[wid - 1] : 0);
    if (i < N) {
        g_rowptr[i + 1] = incl;                     // local inclusive; offset added later
        g_dinv[i] = rsqrtf((float)v + 1.0f);        // +1 self-loop
    }
    if (tid == SCAN_B - 1) g_bsum[blockIdx.x] = incl;  // block total
}

// ---------------- phase 2: exclusive scan of block sums (tiny) --------------
__global__ void bsum_scan_kernel(int nb) {
    if (threadIdx.x == 0 && blockIdx.x == 0) {
        int run = 0;
        for (int b = 0; b < nb; b++) { g_boff[b] = run; run += g_bsum[b]; }
    }
}

// ---------------- phase 3: add block offsets ----------------
__global__ void add_off_kernel(int N) {
    int i = blockIdx.x * blockDim.x + threadIdx.x;
    if (i < N) g_rowptr[i + 1] += g_boff[i / SCAN_B];
    if (i == 0) g_rowptr[0] = 0;
}

// ---------------- counting-sort edges into CSR (grouped by dst) -------------
__global__ void csr_fill_kernel(int E) {
    int e = blockIdx.x * blockDim.x + threadIdx.x;
    if (e >= E) return;
    int d = g_dst[e];
    int pos = g_rowptr[d] + atomicAdd(&g_cnt[d], 1);
    g_csr[pos] = g_src[e];
}

// ---------------- GEMM: g_h[N,128] = (X[N,128] @ W[128,128]) * dinv[row] ----
// 128 threads/CTA (one per output column), 32 rows per CTA in smem.
__global__ __launch_bounds__(128) void gemm128_kernel(
    const float* __restrict__ Xin, int use_agg,
    const float* __restrict__ W, int N)
{
    __shared__ float xs[32][D];
    const float* X = use_agg ? g_agg : Xin;
    const int t  = threadIdx.x;            // output column
    const int r0 = blockIdx.x * 32;
    const int rows = min(32, N - r0);

    {
        const float4* Xv = reinterpret_cast<const float4*>(X + (size_t)r0 * D);
        float4* xsv = reinterpret_cast<float4*>(&xs[0][0]);
        int tot = rows * (D / 4);
        for (int idx = t; idx < tot; idx += 128) xsv[idx] = Xv[idx];
    }
    __syncthreads();

    float acc[32];
#pragma unroll
    for (int r = 0; r < 32; r++) acc[r] = 0.f;

#pragma unroll 4
    for (int kc = 0; kc < D; kc += 8) {
        float w[8];
#pragma unroll
        for (int i = 0; i < 8; i++) w[i] = W[(kc + i) * D + t];
#pragma unroll
        for (int r = 0; r < 32; r++) {
            float4 a = *reinterpret_cast<const float4*>(&xs[r][kc]);
            float4 b = *reinterpret_cast<const float4*>(&xs[r][kc + 4]);
            acc[r] += a.x * w[0] + a.y * w[1] + a.z * w[2] + a.w * w[3]
                    + b.x * w[4] + b.y * w[5] + b.z * w[6] + b.w * w[7];
        }
    }

    for (int r = 0; r < rows; r++)
        g_h[(size_t)(r0 + r) * D + t] = acc[r] * g_dinv[r0 + r];
}

// ---------------- gather aggregation (no atomics) ----------------------------
// out[d] = dinv[d] * (h_scaled[d] + sum_{s in nbr(d)} h_scaled[s]) + bias
// One warp per dst node; lane handles 4 contiguous columns.
__global__ __launch_bounds__(256) void agg_kernel(
    float* __restrict__ out_base, int use_out,
    const float* __restrict__ bias, int N, int do_relu)
{
    int node = (blockIdx.x * blockDim.x + threadIdx.x) >> 5;
    int lane = threadIdx.x & 31;
    if (node >= N) return;

    int beg = g_rowptr[node];
    int end = g_rowptr[node + 1];

    // self-loop term: this row's own pre-scaled value
    float4 acc = *reinterpret_cast<const float4*>(&g_h[(size_t)node * D + lane * 4]);

    for (int j0 = beg; j0 < end; j0 += 32) {
        int jj = j0 + lane;
        int sj = (jj < end) ? g_csr[jj] : 0;
        int cnt = min(32, end - j0);
        for (int k = 0; k < cnt; k++) {
            int s = __shfl_sync(0xffffffffu, sj, k);
            float4 v = *reinterpret_cast<const float4*>(&g_h[(size_t)s * D + lane * 4]);
            acc.x += v.x; acc.y += v.y; acc.z += v.z; acc.w += v.w;
        }
    }

    float dn = g_dinv[node];
    float4 b = *reinterpret_cast<const float4*>(&bias[lane * 4]);
    float4 o;
    o.x = acc.x * dn + b.x;
    o.y = acc.y * dn + b.y;
    o.z = acc.z * dn + b.z;
    o.w = acc.w * dn + b.w;
    if (do_relu) {
        o.x = fmaxf(o.x, 0.f); o.y = fmaxf(o.y, 0.f);
        o.z = fmaxf(o.z, 0.f); o.w = fmaxf(o.w, 0.f);
    }
    float* outp = use_out ? out_base : g_agg;
    *reinterpret_cast<float4*>(&outp[(size_t)node * D + lane * 4]) = o;
}

// ---------------- launch ----------------
extern "C" void kernel_launch(void* const* d_in, const int* in_sizes, int n_in,
                              void* d_out, int out_size) {
    const float* x   = (const float*)d_in[0];
    const void*  ei  = d_in[1];
    const float* W1  = (const float*)d_in[2];
    const float* b1  = (const float*)d_in[3];
    const float* W2  = (const float*)d_in[4];
    const float* b2  = (const float*)d_in[5];
    float*       out = (float*)d_out;

    const int N = in_sizes[0] / D;
    const int E = in_sizes[1] / 2;

    const int TB = 256;
    const int n_blocks    = (N + TB - 1) / TB;
    const int e_blocks    = (E + TB - 1) / TB;
    const int gemm_blocks = (N + 31) / 32;
    const int agg_blocks  = (int)(((long)N * 32 + TB - 1) / TB);
    const int scan_blocks = (N + SCAN_B - 1) / SCAN_B;

    // ---- graph preprocessing (shared by both layers) ----
    init_kernel<<<n_blocks, TB>>>(N);
    detect_kernel<<<e_blocks, TB>>>((const unsigned long long*)ei, E / 2,
                                    (unsigned long long)N);
    decode_kernel<<<e_blocks, TB>>>(ei, E);
    block_scan_kernel<<<scan_blocks, SCAN_B>>>(N);
    bsum_scan_kernel<<<1, 32>>>(scan_blocks);
    add_off_kernel<<<n_blocks, TB>>>(N);
    csr_fill_kernel<<<e_blocks, TB>>>(E);

    // ---- layer 1: h = (x@W1)*dinv ; agg = relu(dinv*(self+nbrs) + b1) ----
    gemm128_kernel<<<gemm_blocks, 128>>>(x, 0, W1, N);
    agg_kernel<<<agg_blocks, TB>>>(out, 0, b1, N, 1);

    // ---- layer 2: h = (agg@W2)*dinv ; out = dinv*(self+nbrs) + b2 ----
    gemm128_kernel<<<gemm_blocks, 128>>>(x, 1, W2, N);
    agg_kernel<<<agg_blocks, TB>>>(out, 1, b2, N, 0);
}

// round 6
// speedup vs baseline: 2.1961x; 1.0310x over previous
#include <cuda_runtime.h>
#include <cuda_bf16.h>
#include <cstdint>

#define D 128
#define MAXN 50051
#define MAXE 700000
#define SCAN_B 1024

// ---------------- scratch (no allocations allowed) ----------------
__device__ float g_h[(size_t)MAXN * D];    // GEMM out, pre-scaled by dinv[row]
__device__ float g_agg[(size_t)MAXN * D];  // layer-1 activation
__device__ float g_dinv[MAXN];
__device__ int   g_degi[MAXN];
__device__ int   g_cnt[MAXN];
__device__ int   g_rowptr[MAXN + 1];
__device__ int   g_src[MAXE];
__device__ int   g_dst[MAXE];
__device__ int   g_csr[MAXE];
__device__ int   g_bsum[128];
__device__ int   g_boff[128];
__device__ int   g_is32;
// W split to bf16 hi/lo, transposed to [n][k] row-major (plain, no swizzle)
__device__ __nv_bfloat16 g_WhT[2][D * D];
__device__ __nv_bfloat16 g_WlT[2][D * D];

// ---------------- init: zero histograms + flag ----------------
__global__ void init_kernel(int N) {
    int i = blockIdx.x * blockDim.x + threadIdx.x;
    if (i < N) { g_degi[i] = 0; g_cnt[i] = 0; }
    if (i == 0) g_is32 = 0;
}

// ---------------- edge dtype detection ----------------
__global__ void detect_kernel(const unsigned long long* __restrict__ ei,
                              int n, unsigned long long limit) {
    int e = blockIdx.x * blockDim.x + threadIdx.x;
    if (e < n && ei[e] >= limit) atomicOr(&g_is32, 1);
}

// ---------------- decode edges + in-degree histogram ----------------
__global__ void decode_kernel(const void* __restrict__ ei, int E) {
    int e = blockIdx.x * blockDim.x + threadIdx.x;
    if (e >= E) return;
    int s, d;
    if (g_is32) {
        const int* p = (const int*)ei;
        s = p[e]; d = p[E + e];
    } else {
        const long long* p = (const long long*)ei;
        s = (int)p[e]; d = (int)p[E + e];
    }
    g_src[e] = s;
    g_dst[e] = d;
    atomicAdd(&g_degi[d], 1);
}

// ---------------- W split: fp32 -> bf16 hi/lo + transpose to [n][k] ---------
__global__ void wsplit_kernel(const float* __restrict__ W1,
                              const float* __restrict__ W2) {
    int idx = blockIdx.x * blockDim.x + threadIdx.x;
    if (idx >= 2 * D * D) return;
    int m = idx >> 14;
    int e = idx & (D * D - 1);
    int k = e >> 7, n = e & 127;       // W[k][n]
    float v = (m ? W2 : W1)[k * D + n];
    __nv_bfloat16 hi = __float2bfloat16(v);
    __nv_bfloat16 lo = __float2bfloat16(v - __bfloat162float(hi));
    g_WhT[m][n * D + k] = hi;
    g_WlT[m][n * D + k] = lo;
}

// ---------------- scan phases (unchanged) ----------------
__global__ __launch_bounds__(SCAN_B) void block_scan_kernel(int N) {
    __shared__ int wsum[SCAN_B / 32];
    int tid = threadIdx.x, lane = tid & 31, wid = tid >> 5;
    int i = blockIdx.x * SCAN_B + tid;
    int v = (i < N) ? g_degi[i] : 0;
    int s = v;
#pragma unroll
    for (int o = 1; o < 32; o <<= 1) {
        int t = __shfl_up_sync(0xffffffffu, s, o);
        if (lane >= o) s += t;
    }
    if (lane == 31) wsum[wid] = s;
    __syncthreads();
    if (wid == 0) {
        int ws = wsum[lane];
#pragma unroll
        for (int o = 1; o < 32; o <<= 1) {
            int t = __shfl_up_sync(0xffffffffu, ws, o);
            if (lane >= o) ws += t;
        }
        wsum[lane] = ws;
    }
    __syncthreads();
    int incl = s + (wid > 0 ? wsum[wid - 1] : 0);
    if (i < N) {
        g_rowptr[i + 1] = incl;
        g_dinv[i] = rsqrtf((float)v + 1.0f);
    }
    if (tid == SCAN_B - 1) g_bsum[blockIdx.x] = incl;
}

__global__ void bsum_scan_kernel(int nb) {
    if (threadIdx.x == 0 && blockIdx.x == 0) {
        int run = 0;
        for (int b = 0; b < nb; b++) { g_boff[b] = run; run += g_bsum[b]; }
    }
}

__global__ void add_off_kernel(int N) {
    int i = blockIdx.x * blockDim.x + threadIdx.x;
    if (i < N) g_rowptr[i + 1] += g_boff[i / SCAN_B];
    if (i == 0) g_rowptr[0] = 0;
}

__global__ void csr_fill_kernel(int E) {
    int e = blockIdx.x * blockDim.x + threadIdx.x;
    if (e >= E) return;
    int d = g_dst[e];
    int pos = g_rowptr[d] + atomicAdd(&g_cnt[d], 1);
    g_csr[pos] = g_src[e];
}

// ---------------- mma.sync bf16-split GEMM: g_h = (X @ W) * dinv[row] -------
// CTA: 128 threads / 4 warps, 64 rows. Warp w computes rows [16w, 16w+16).
// D = Ah*Bh + Ah*Bl + Al*Bh in fp32 accumulators (m16n8k16 bf16 mma.sync).
__device__ __forceinline__ void mma16816(float& c0, float& c1, float& c2, float& c3,
                                         uint32_t a0, uint32_t a1, uint32_t a2, uint32_t a3,
                                         uint32_t b0, uint32_t b1) {
    asm volatile(
        "mma.sync.aligned.m16n8k16.row.col.f32.bf16.bf16.f32 "
        "{%0,%1,%2,%3}, {%4,%5,%6,%7}, {%8,%9}, {%0,%1,%2,%3};"
        : "+f"(c0), "+f"(c1), "+f"(c2), "+f"(c3)
        : "r"(a0), "r"(a1), "r"(a2), "r"(a3), "r"(b0), "r"(b1));
}

__global__ __launch_bounds__(128) void gemm_mma_kernel(
    const float* __restrict__ Xin, int use_agg, int wsel, int N)
{
    // 64 rows x 64 u32 words (2 bf16 each), pitch 66 to de-conflict banks
    __shared__ uint32_t sAh[64][66];
    __shared__ uint32_t sAl[64][66];

    const float* X = use_agg ? g_agg : Xin;
    int t = threadIdx.x, wid = t >> 5, lane = t & 31;
    int r0 = blockIdx.x * 64;

    // --- fill SMEM: load X rows, split fp32 -> bf16 hi/lo ---
#pragma unroll 4
    for (int i = 0; i < 32; i++) {
        int idx = i * 128 + t;            // 0..4095
        int row = idx >> 6, w = idx & 63; // word index (2 floats)
        int gr = r0 + row;
        float2 v = (gr < N) ? *(const float2*)(X + (size_t)gr * D + w * 2)
                            : make_float2(0.f, 0.f);
        __nv_bfloat16 h0 = __float2bfloat16(v.x);
        __nv_bfloat16 h1 = __float2bfloat16(v.y);
        __nv_bfloat16 l0 = __float2bfloat16(v.x - __bfloat162float(h0));
        __nv_bfloat16 l1 = __float2bfloat16(v.y - __bfloat162float(h1));
        sAh[row][w] = ((uint32_t)__bfloat16_as_ushort(h1) << 16) | __bfloat16_as_ushort(h0);
        sAl[row][w] = ((uint32_t)__bfloat16_as_ushort(l1) << 16) | __bfloat16_as_ushort(l0);
    }
    __syncthreads();

    // --- preload A fragments (n-invariant): 8 k-blocks x 4 regs, hi + lo ---
    int qrow = wid * 16 + (lane >> 2);   // a0 row in CTA tile
    int kq   = lane & 3;                 // word offset within k16 block
    uint32_t ah[8][4], al[8][4];
#pragma unroll
    for (int kb = 0; kb < 8; kb++) {
        int kw = kb * 8 + kq;
        ah[kb][0] = sAh[qrow][kw];
        ah[kb][1] = sAh[qrow + 8][kw];
        ah[kb][2] = sAh[qrow][kw + 4];
        ah[kb][3] = sAh[qrow + 8][kw + 4];
        al[kb][0] = sAl[qrow][kw];
        al[kb][1] = sAl[qrow + 8][kw];
        al[kb][2] = sAl[qrow][kw + 4];
        al[kb][3] = sAl[qrow + 8][kw + 4];
    }

    int gr0 = r0 + qrow;
    int gr1 = gr0 + 8;
    float dv0 = (gr0 < N) ? g_dinv[gr0] : 0.f;
    float dv1 = (gr1 < N) ? g_dinv[gr1] : 0.f;

    const uint32_t* WTh = (const uint32_t*)g_WhT[wsel];
    const uint32_t* WTl = (const uint32_t*)g_WlT[wsel];
    int brow = lane >> 2;                // n within 8-block

    // --- n-blocks: 16 x (8 k-blocks x 3 mmas) ---
#pragma unroll 2
    for (int nb = 0; nb < 16; nb++) {
        float c0 = 0.f, c1 = 0.f, c2 = 0.f, c3 = 0.f;
        const uint32_t* wh = WTh + (nb * 8 + brow) * (D / 2);
        const uint32_t* wl = WTl + (nb * 8 + brow) * (D / 2);
#pragma unroll
        for (int kb = 0; kb < 8; kb++) {
            int kw = kb * 8 + kq;
            uint32_t bh0 = wh[kw], bh1 = wh[kw + 4];
            uint32_t bl0 = wl[kw], bl1 = wl[kw + 4];
            mma16816(c0, c1, c2, c3, ah[kb][0], ah[kb][1], ah[kb][2], ah[kb][3], bh0, bh1);
            mma16816(c0, c1, c2, c3, ah[kb][0], ah[kb][1], ah[kb][2], ah[kb][3], bl0, bl1);
            mma16816(c0, c1, c2, c3, al[kb][0], al[kb][1], al[kb][2], al[kb][3], bh0, bh1);
        }
        int col = nb * 8 + (lane & 3) * 2;
        if (gr0 < N)
            *(float2*)(&g_h[(size_t)gr0 * D + col]) = make_float2(c0 * dv0, c1 * dv0);
        if (gr1 < N)
            *(float2*)(&g_h[(size_t)gr1 * D + col]) = make_float2(c2 * dv1, c3 * dv1);
    }
}

// ---------------- gather aggregation (unchanged) ----------------------------
__global__ __launch_bounds__(256) void agg_kernel(
    float* __restrict__ out_base, int use_out,
    const float* __restrict__ bias, int N, int do_relu)
{
    int node = (blockIdx.x * blockDim.x + threadIdx.x) >> 5;
    int lane = threadIdx.x & 31;
    if (node >= N) return;

    int beg = g_rowptr[node];
    int end = g_rowptr[node + 1];

    float4 acc = *reinterpret_cast<const float4*>(&g_h[(size_t)node * D + lane * 4]);

    for (int j0 = beg; j0 < end; j0 += 32) {
        int jj = j0 + lane;
        int sj = (jj < end) ? g_csr[jj] : 0;
        int cnt = min(32, end - j0);
        for (int k = 0; k < cnt; k++) {
            int s = __shfl_sync(0xffffffffu, sj, k);
            float4 v = *reinterpret_cast<const float4*>(&g_h[(size_t)s * D + lane * 4]);
            acc.x += v.x; acc.y += v.y; acc.z += v.z; acc.w += v.w;
        }
    }

    float dn = g_dinv[node];
    float4 b = *reinterpret_cast<const float4*>(&bias[lane * 4]);
    float4 o;
    o.x = acc.x * dn + b.x;
    o.y = acc.y * dn + b.y;
    o.z = acc.z * dn + b.z;
    o.w = acc.w * dn + b.w;
    if (do_relu) {
        o.x = fmaxf(o.x, 0.f); o.y = fmaxf(o.y, 0.f);
        o.z = fmaxf(o.z, 0.f); o.w = fmaxf(o.w, 0.f);
    }
    float* outp = use_out ? out_base : g_agg;
    *reinterpret_cast<float4*>(&outp[(size_t)node * D + lane * 4]) = o;
}

// ---------------- launch ----------------
extern "C" void kernel_launch(void* const* d_in, const int* in_sizes, int n_in,
                              void* d_out, int out_size) {
    const float* x   = (const float*)d_in[0];
    const void*  ei  = d_in[1];
    const float* W1  = (const float*)d_in[2];
    const float* b1  = (const float*)d_in[3];
    const float* W2  = (const float*)d_in[4];
    const float* b2  = (const float*)d_in[5];
    float*       out = (float*)d_out;

    const int N = in_sizes[0] / D;
    const int E = in_sizes[1] / 2;

    const int TB = 256;
    const int n_blocks    = (N + TB - 1) / TB;
    const int e_blocks    = (E + TB - 1) / TB;
    const int agg_blocks  = (int)(((long)N * 32 + TB - 1) / TB);
    const int scan_blocks = (N + SCAN_B - 1) / SCAN_B;
    const int mma_blocks  = (N + 63) / 64;

    // ---- graph preprocessing + W split (shared by both layers) ----
    wsplit_kernel<<<(2 * D * D + TB - 1) / TB, TB>>>(W1, W2);
    init_kernel<<<n_blocks, TB>>>(N);
    detect_kernel<<<e_blocks, TB>>>((const unsigned long long*)ei, E / 2,
                                    (unsigned long long)N);
    decode_kernel<<<e_blocks, TB>>>(ei, E);
    block_scan_kernel<<<scan_blocks, SCAN_B>>>(N);
    bsum_scan_kernel<<<1, 32>>>(scan_blocks);
    add_off_kernel<<<n_blocks, TB>>>(N);
    csr_fill_kernel<<<e_blocks, TB>>>(E);

    // ---- layer 1 ----
    gemm_mma_kernel<<<mma_blocks, 128>>>(x, 0, 0, N);
    agg_kernel<<<agg_blocks, TB>>>(out, 0, b1, N, 1);

    // ---- layer 2 ----
    gemm_mma_kernel<<<mma_blocks, 128>>>(x, 1, 1, N);
    agg_kernel<<<agg_blocks, TB>>>(out, 1, b2, N, 0);
}

// round 7
// speedup vs baseline: 3.4732x; 1.5815x over previous
#include <cuda_runtime.h>
#include <cuda_bf16.h>
#include <cstdint>

#define D 128
#define MAXN 50051
#define MAXE 700000
#define SCAN_B 1024

// ---------------- scratch (no allocations allowed) ----------------
__device__ float g_h[(size_t)MAXN * D];    // GEMM out, pre-scaled by dinv[row]
__device__ float g_agg[(size_t)MAXN * D];  // layer-1 activation
__device__ float g_dinv[MAXN];
__device__ int   g_degi[MAXN];
__device__ int   g_cnt[MAXN];
__device__ int   g_rowptr[MAXN + 1];
__device__ int   g_src[MAXE];
__device__ int   g_dst[MAXE];
__device__ int   g_csr[MAXE];
__device__ int   g_bsum[128];
__device__ int   g_boff[128];
__device__ int   g_is32;
// Pre-packed per-lane mma.sync B fragments: [matrix][(nb*8+kb)*32+lane]
// uint4 = {bh0, bh1, bl0, bl1} (hi/lo bf16 split)
__device__ uint4 g_Wpack[2][16 * 8 * 32];

// ---------------- init: zero histograms + flag ----------------
__global__ void init_kernel(int N) {
    int i = blockIdx.x * blockDim.x + threadIdx.x;
    if (i < N) { g_degi[i] = 0; g_cnt[i] = 0; }
    if (i == 0) g_is32 = 0;
}

// ---------------- edge dtype detection ----------------
__global__ void detect_kernel(const unsigned long long* __restrict__ ei,
                              int n, unsigned long long limit) {
    int e = blockIdx.x * blockDim.x + threadIdx.x;
    if (e < n && ei[e] >= limit) atomicOr(&g_is32, 1);
}

// ---------------- decode edges + in-degree histogram ----------------
__global__ void decode_kernel(const void* __restrict__ ei, int E) {
    int e = blockIdx.x * blockDim.x + threadIdx.x;
    if (e >= E) return;
    int s, d;
    if (g_is32) {
        const int* p = (const int*)ei;
        s = p[e]; d = p[E + e];
    } else {
        const long long* p = (const long long*)ei;
        s = (int)p[e]; d = (int)p[E + e];
    }
    g_src[e] = s;
    g_dst[e] = d;
    atomicAdd(&g_degi[d], 1);
}

// ---------------- W split + pack per-lane B fragments ----------------
// One thread per (matrix, nb, kb, lane). b0 covers k = kb*16 + kq*2 (+1),
// b1 covers k + 8, row n = nb*8 + brow.  (Mapping validated in round 6.)
__global__ void wsplit_kernel(const float* __restrict__ W1,
                              const float* __restrict__ W2) {
    int tid = blockIdx.x * blockDim.x + threadIdx.x;
    if (tid >= 2 * 16 * 8 * 32) return;
    int m    = tid >> 12;
    int rem  = tid & 4095;
    int nb   = rem >> 8;
    int kb   = (rem >> 5) & 7;
    int lane = rem & 31;
    int brow = lane >> 2, kq = lane & 3;
    int n  = nb * 8 + brow;
    int k0 = kb * 16 + kq * 2;     // b0 element pair
    int k1 = k0 + 8;               // b1 element pair

    const float* W = m ? W2 : W1;
    float v00 = W[k0 * D + n],       v01 = W[(k0 + 1) * D + n];
    float v10 = W[k1 * D + n],       v11 = W[(k1 + 1) * D + n];

    __nv_bfloat16 h00 = __float2bfloat16(v00), h01 = __float2bfloat16(v01);
    __nv_bfloat16 h10 = __float2bfloat16(v10), h11 = __float2bfloat16(v11);
    __nv_bfloat16 l00 = __float2bfloat16(v00 - __bfloat162float(h00));
    __nv_bfloat16 l01 = __float2bfloat16(v01 - __bfloat162float(h01));
    __nv_bfloat16 l10 = __float2bfloat16(v10 - __bfloat162float(h10));
    __nv_bfloat16 l11 = __float2bfloat16(v11 - __bfloat162float(h11));

    uint4 pk;
    pk.x = ((uint32_t)__bfloat16_as_ushort(h01) << 16) | __bfloat16_as_ushort(h00);
    pk.y = ((uint32_t)__bfloat16_as_ushort(h11) << 16) | __bfloat16_as_ushort(h10);
    pk.z = ((uint32_t)__bfloat16_as_ushort(l01) << 16) | __bfloat16_as_ushort(l00);
    pk.w = ((uint32_t)__bfloat16_as_ushort(l11) << 16) | __bfloat16_as_ushort(l10);
    g_Wpack[m][(nb * 8 + kb) * 32 + lane] = pk;
}

// ---------------- scan phases (unchanged) ----------------
__global__ __launch_bounds__(SCAN_B) void block_scan_kernel(int N) {
    __shared__ int wsum[SCAN_B / 32];
    int tid = threadIdx.x, lane = tid & 31, wid = tid >> 5;
    int i = blockIdx.x * SCAN_B + tid;
    int v = (i < N) ? g_degi[i] : 0;
    int s = v;
#pragma unroll
    for (int o = 1; o < 32; o <<= 1) {
        int t = __shfl_up_sync(0xffffffffu, s, o);
        if (lane >= o) s += t;
    }
    if (lane == 31) wsum[wid] = s;
    __syncthreads();
    if (wid == 0) {
        int ws = wsum[lane];
#pragma unroll
        for (int o = 1; o < 32; o <<= 1) {
            int t = __shfl_up_sync(0xffffffffu, ws, o);
            if (lane >= o) ws += t;
        }
        wsum[lane] = ws;
    }
    __syncthreads();
    int incl = s + (wid > 0 ? wsum[wid - 1] : 0);
    if (i < N) {
        g_rowptr[i + 1] = incl;
        g_dinv[i] = rsqrtf((float)v + 1.0f);
    }
    if (tid == SCAN_B - 1) g_bsum[blockIdx.x] = incl;
}

__global__ void bsum_scan_kernel(int nb) {
    if (threadIdx.x == 0 && blockIdx.x == 0) {
        int run = 0;
        for (int b = 0; b < nb; b++) { g_boff[b] = run; run += g_bsum[b]; }
    }
}

__global__ void add_off_kernel(int N) {
    int i = blockIdx.x * blockDim.x + threadIdx.x;
    if (i < N) g_rowptr[i + 1] += g_boff[i / SCAN_B];
    if (i == 0) g_rowptr[0] = 0;
}

__global__ void csr_fill_kernel(int E) {
    int e = blockIdx.x * blockDim.x + threadIdx.x;
    if (e >= E) return;
    int d = g_dst[e];
    int pos = g_rowptr[d] + atomicAdd(&g_cnt[d], 1);
    g_csr[pos] = g_src[e];
}

// ---------------- mma.sync bf16-split GEMM: g_h = (X @ W) * dinv[row] -------
__device__ __forceinline__ void mma16816(float& c0, float& c1, float& c2, float& c3,
                                         uint32_t a0, uint32_t a1, uint32_t a2, uint32_t a3,
                                         uint32_t b0, uint32_t b1) {
    asm volatile(
        "mma.sync.aligned.m16n8k16.row.col.f32.bf16.bf16.f32 "
        "{%0,%1,%2,%3}, {%4,%5,%6,%7}, {%8,%9}, {%0,%1,%2,%3};"
        : "+f"(c0), "+f"(c1), "+f"(c2), "+f"(c3)
        : "r"(a0), "r"(a1), "r"(a2), "r"(a3), "r"(b0), "r"(b1));
}

__global__ __launch_bounds__(128) void gemm_mma_kernel(
    const float* __restrict__ Xin, int use_agg, int wsel, int N)
{
    // pitch 68: bank = (68*row + w) % 32 = (4*(row%8) + w%4 ...) conflict-free
    __shared__ uint32_t sAh[64][68];
    __shared__ uint32_t sAl[64][68];

    const float* X = use_agg ? g_agg : Xin;
    int t = threadIdx.x, wid = t >> 5, lane = t & 31;
    int r0 = blockIdx.x * 64;

    // --- fill SMEM: load X rows, split fp32 -> bf16 hi/lo ---
#pragma unroll 4
    for (int i = 0; i < 32; i++) {
        int idx = i * 128 + t;
        int row = idx >> 6, w = idx & 63;
        int gr = r0 + row;
        float2 v = (gr < N) ? *(const float2*)(X + (size_t)gr * D + w * 2)
                            : make_float2(0.f, 0.f);
        __nv_bfloat16 h0 = __float2bfloat16(v.x);
        __nv_bfloat16 h1 = __float2bfloat16(v.y);
        __nv_bfloat16 l0 = __float2bfloat16(v.x - __bfloat162float(h0));
        __nv_bfloat16 l1 = __float2bfloat16(v.y - __bfloat162float(h1));
        sAh[row][w] = ((uint32_t)__bfloat16_as_ushort(h1) << 16) | __bfloat16_as_ushort(h0);
        sAl[row][w] = ((uint32_t)__bfloat16_as_ushort(l1) << 16) | __bfloat16_as_ushort(l0);
    }
    __syncthreads();

    // --- preload A fragments (n-invariant): 8 k-blocks x 4 regs, hi + lo ---
    int qrow = wid * 16 + (lane >> 2);
    int kq   = lane & 3;
    uint32_t ah[8][4], al[8][4];
#pragma unroll
    for (int kb = 0; kb < 8; kb++) {
        int kw = kb * 8 + kq;
        ah[kb][0] = sAh[qrow][kw];
        ah[kb][1] = sAh[qrow + 8][kw];
        ah[kb][2] = sAh[qrow][kw + 4];
        ah[kb][3] = sAh[qrow + 8][kw + 4];
        al[kb][0] = sAl[qrow][kw];
        al[kb][1] = sAl[qrow + 8][kw];
        al[kb][2] = sAl[qrow][kw + 4];
        al[kb][3] = sAl[qrow + 8][kw + 4];
    }

    int gr0 = r0 + qrow;
    int gr1 = gr0 + 8;
    float dv0 = (gr0 < N) ? g_dinv[gr0] : 0.f;
    float dv1 = (gr1 < N) ? g_dinv[gr1] : 0.f;

    const uint4* wp = g_Wpack[wsel];

    // --- n-blocks: 16 x (8 k-blocks: 1 coalesced LDG.128 + 3 mmas) ---
#pragma unroll 2
    for (int nb = 0; nb < 16; nb++) {
        float c0 = 0.f, c1 = 0.f, c2 = 0.f, c3 = 0.f;
        const uint4* wrow = wp + nb * 8 * 32 + lane;
#pragma unroll
        for (int kb = 0; kb < 8; kb++) {
            uint4 b = __ldg(wrow + kb * 32);
            mma16816(c0, c1, c2, c3, ah[kb][0], ah[kb][1], ah[kb][2], ah[kb][3], b.x, b.y);
            mma16816(c0, c1, c2, c3, ah[kb][0], ah[kb][1], ah[kb][2], ah[kb][3], b.z, b.w);
            mma16816(c0, c1, c2, c3, al[kb][0], al[kb][1], al[kb][2], al[kb][3], b.x, b.y);
        }
        int col = nb * 8 + (lane & 3) * 2;
        if (gr0 < N)
            *(float2*)(&g_h[(size_t)gr0 * D + col]) = make_float2(c0 * dv0, c1 * dv0);
        if (gr1 < N)
            *(float2*)(&g_h[(size_t)gr1 * D + col]) = make_float2(c2 * dv1, c3 * dv1);
    }
}

// ---------------- gather aggregation: dual-accumulator unroll ----------------
__global__ __launch_bounds__(256) void agg_kernel(
    float* __restrict__ out_base, int use_out,
    const float* __restrict__ bias, int N, int do_relu)
{
    int node = (blockIdx.x * blockDim.x + threadIdx.x) >> 5;
    int lane = threadIdx.x & 31;
    if (node >= N) return;

    int beg = g_rowptr[node];
    int end = g_rowptr[node + 1];

    const float* hp = g_h;
    float4 acc = *(const float4*)(hp + (size_t)node * D + lane * 4);
    float4 acc2 = make_float4(0.f, 0.f, 0.f, 0.f);

    for (int j0 = beg; j0 < end; j0 += 32) {
        int jj = j0 + lane;
        int sj = (jj < end) ? g_csr[jj] : 0;
        int cnt = min(32, end - j0);
        int k = 0;
        for (; k + 1 < cnt; k += 2) {
            int s0 = __shfl_sync(0xffffffffu, sj, k);
            int s1 = __shfl_sync(0xffffffffu, sj, k + 1);
            float4 v0 = __ldg((const float4*)(hp + (size_t)s0 * D + lane * 4));
            float4 v1 = __ldg((const float4*)(hp + (size_t)s1 * D + lane * 4));
            acc.x += v0.x;  acc.y += v0.y;  acc.z += v0.z;  acc.w += v0.w;
            acc2.x += v1.x; acc2.y += v1.y; acc2.z += v1.z; acc2.w += v1.w;
        }
        if (k < cnt) {
            int s0 = __shfl_sync(0xffffffffu, sj, k);
            float4 v0 = __ldg((const float4*)(hp + (size_t)s0 * D + lane * 4));
            acc.x += v0.x; acc.y += v0.y; acc.z += v0.z; acc.w += v0.w;
        }
    }
    acc.x += acc2.x; acc.y += acc2.y; acc.z += acc2.z; acc.w += acc2.w;

    float dn = g_dinv[node];
    float4 b = *(const float4*)(&bias[lane * 4]);
    float4 o;
    o.x = acc.x * dn + b.x;
    o.y = acc.y * dn + b.y;
    o.z = acc.z * dn + b.z;
    o.w = acc.w * dn + b.w;
    if (do_relu) {
        o.x = fmaxf(o.x, 0.f); o.y = fmaxf(o.y, 0.f);
        o.z = fmaxf(o.z, 0.f); o.w = fmaxf(o.w, 0.f);
    }
    float* outp = use_out ? out_base : g_agg;
    *(float4*)(&outp[(size_t)node * D + lane * 4]) = o;
}

// ---------------- launch ----------------
extern "C" void kernel_launch(void* const* d_in, const int* in_sizes, int n_in,
                              void* d_out, int out_size) {
    const float* x   = (const float*)d_in[0];
    const void*  ei  = d_in[1];
    const float* W1  = (const float*)d_in[2];
    const float* b1  = (const float*)d_in[3];
    const float* W2  = (const float*)d_in[4];
    const float* b2  = (const float*)d_in[5];
    float*       out = (float*)d_out;

    const int N = in_sizes[0] / D;
    const int E = in_sizes[1] / 2;

    const int TB = 256;
    const int n_blocks    = (N + TB - 1) / TB;
    const int e_blocks    = (E + TB - 1) / TB;
    const int agg_blocks  = (int)(((long)N * 32 + TB - 1) / TB);
    const int scan_blocks = (N + SCAN_B - 1) / SCAN_B;
    const int mma_blocks  = (N + 63) / 64;

    // ---- graph preprocessing + W fragment pack (shared by both layers) ----
    wsplit_kernel<<<(2 * 16 * 8 * 32 + TB - 1) / TB, TB>>>(W1, W2);
    init_kernel<<<n_blocks, TB>>>(N);
    detect_kernel<<<e_blocks, TB>>>((const unsigned long long*)ei, E / 2,
                                    (unsigned long long)N);
    decode_kernel<<<e_blocks, TB>>>(ei, E);
    block_scan_kernel<<<scan_blocks, SCAN_B>>>(N);
    bsum_scan_kernel<<<1, 32>>>(scan_blocks);
    add_off_kernel<<<n_blocks, TB>>>(N);
    csr_fill_kernel<<<e_blocks, TB>>>(E);

    // ---- layer 1 ----
    gemm_mma_kernel<<<mma_blocks, 128>>>(x, 0, 0, N);
    agg_kernel<<<agg_blocks, TB>>>(out, 0, b1, N, 1);

    // ---- layer 2 ----
    gemm_mma_kernel<<<mma_blocks, 128>>>(x, 1, 1, N);
    agg_kernel<<<agg_blocks, TB>>>(out, 1, b2, N, 0);
}